// round 2
// baseline (speedup 1.0000x reference)
#include <cuda_runtime.h>

// ---------------- problem constants ----------------
#define HN   512      // hidden
#define BB   256      // batch
#define G4   2048     // 4*H
#define TENC 512
#define TDEC 96
#define NCTA 128
#define NTHR 256
#define KB   16       // K-chunk

// packed f32x2 FMA (SASS FFMA2) — PTX-only pattern
#define FFMA2(d, a, b) \
    asm("fma.rn.f32x2 %0, %1, %2, %0;" : "+l"(d) : "l"(a), "l"(b))

__device__ __forceinline__ float2 unpack2(unsigned long long v) {
    float2 r;
    asm("mov.b64 {%0, %1}, %2;" : "=f"(r.x), "=f"(r.y) : "l"(v));
    return r;
}

// ---------------- device scratch (static: allocation rules) ----------------
__device__ __align__(16) float d_encW0p[576 * G4];
__device__ __align__(16) float d_encW1p[1024 * G4];
__device__ __align__(16) float d_decW0p[512 * G4];
__device__ __align__(16) float d_decW1p[1024 * G4];
__device__ __align__(16) float d_wx0[G4];
__device__ __align__(16) float d_be0[G4];
__device__ __align__(16) float d_be1[G4];
__device__ __align__(16) float d_bd0[G4];
__device__ __align__(16) float d_bd1[G4];
__device__ __align__(16) float d_fcW0t[512 * 512];
__device__ __align__(16) float d_srcT[TENC * 64 * BB];     // [t*64+k][m]
__device__ __align__(16) float d_h0T[2][HN * BB];          // [k][m], double buffered
__device__ __align__(16) float d_h1T[2][HN * BB];
__device__ __align__(16) float d_c0T[HN * BB];
__device__ __align__(16) float d_c1T[HN * BB];
__device__ __align__(16) float d_o1T[HN * BB];             // fc hidden, [n][m]
__device__ __align__(16) float d_xdec[BB];
__device__ unsigned g_gen;     // barrier generation (reset each launch by pack_misc)
__device__ unsigned g_arrive;  // arrival counter    (reset each launch by pack_misc)

// ---------------- packing kernels ----------------
// Pack one LSTM layer: Wp[k][n] (n = j*4+g, g in torch order i,f,g,o),
// rows k<kin from Wih, k in [kin,kin+512) from Whh. bsum[n] = bih+bhh.
__global__ void pack_lstm(const float* __restrict__ Wih, const float* __restrict__ Whh,
                          const float* __restrict__ bih, const float* __restrict__ bhh,
                          int kin, int sel)
{
    float* Wp = (sel == 0) ? d_encW0p : (sel == 1) ? d_encW1p : (sel == 2) ? d_decW0p : d_decW1p;
    float* bs = (sel == 0) ? d_be0    : (sel == 1) ? d_be1    : (sel == 2) ? d_bd0    : d_bd1;
    int K = kin + HN;
    int total = K * G4;
    for (int idx = blockIdx.x * blockDim.x + threadIdx.x; idx < total;
         idx += gridDim.x * blockDim.x) {
        int k = idx >> 11;          // /2048
        int n = idx & 2047;
        int j = n >> 2, g = n & 3;
        int row = g * HN + j;
        float v = (k < kin) ? Wih[(long long)row * kin + k]
                            : Whh[(long long)row * HN + (k - kin)];
        Wp[idx] = v;
    }
    int t = blockIdx.x * blockDim.x + threadIdx.x;
    if (t < G4) {
        int j = t >> 2, g = t & 3;
        int row = g * HN + j;
        bs[t] = bih[row] + bhh[row];
    }
}

__global__ void pack_misc(const float* __restrict__ src, const float* __restrict__ tgt,
                          const float* __restrict__ decWih0, const float* __restrict__ fcW0)
{
    // reset grid-barrier state every launch (stream-ordered before lstm_main)
    if (blockIdx.x == 0 && threadIdx.x == 0) { g_gen = 0u; g_arrive = 0u; }

    const long long N_SRC = (long long)TENC * 64 * BB;   // 8388608
    const long long N_FC  = 512 * 512;                   // 262144
    const long long N_WX  = G4;                          // 2048
    const long long N_Z   = 6LL * HN * BB;               // 786432
    const long long TOTAL = N_SRC + N_FC + N_WX + N_Z + BB;
    for (long long idx = (long long)blockIdx.x * blockDim.x + threadIdx.x; idx < TOTAL;
         idx += (long long)gridDim.x * blockDim.x) {
        long long i = idx;
        if (i < N_SRC) {
            int tk = (int)(i >> 8);
            int m  = (int)(i & 255);
            d_srcT[i] = src[(long long)m * (TENC * 64) + tk];
            continue;
        }
        i -= N_SRC;
        if (i < N_FC) {      // d_fcW0t[k*512+n] = fcW0[n*512+k]
            int n = (int)(i & 511);
            int k = (int)(i >> 9);
            d_fcW0t[i] = fcW0[n * 512 + k];
            continue;
        }
        i -= N_FC;
        if (i < N_WX) {      // d_wx0[j*4+g] = dec_Wih0[g*512+j]  ([2048][1])
            int j = (int)(i >> 2), g = (int)(i & 3);
            d_wx0[i] = decWih0[g * HN + j];
            continue;
        }
        i -= N_WX;
        if (i < N_Z) {
            int which = (int)(i / (HN * BB));
            int off   = (int)(i % (HN * BB));
            float* p = (which == 0) ? d_h0T[0] : (which == 1) ? d_h0T[1] :
                       (which == 2) ? d_h1T[0] : (which == 3) ? d_h1T[1] :
                       (which == 4) ? d_c0T    : d_c1T;
            p[off] = 0.f;
            continue;
        }
        i -= N_Z;
        d_xdec[i] = tgt[i * TDEC];   // tgt[:,0]
    }
}

// ---------------- main persistent kernel ----------------
__device__ __forceinline__ float sigf(float x) { return 1.f / (1.f + expf(-x)); }

// One LSTM layer-step for this CTA's tile:
//   gates = [A0 | A1] @ Wp + bias (+ x*wx) -> cell -> hT_out, cT (in place)
// A0/A1 are k-major [K][256]. Tile: rows m0..m0+63, hidden j0..j0+15 (all 4 gates).
// Thread (tr=tid>>4, tc=tid&15): rows m0+tr*4..+4, hidden j0+tc.
// Inner product uses packed f32x2 FMA: A duplicated in shared, W pairs natural.
__device__ __forceinline__ void lstm_phase(
    const float* __restrict__ A0, int A0k,
    const float* __restrict__ A1, int A1k,
    const float* __restrict__ Wp,
    const float* __restrict__ bias,
    const float* __restrict__ xvec, const float* __restrict__ wxp,
    float* __restrict__ cT, float* __restrict__ hT_out,
    int m0, int j0, int tid, int tc, int rloc,
    float* As2, float* Ws)
{
    unsigned long long acc[4][2];
#pragma unroll
    for (int r = 0; r < 4; r++) { acc[r][0] = 0ull; acc[r][1] = 0ull; }

    const int K = A0k + A1k;
    const int skk = tid >> 4;            // 0..15 : k within chunk
    const int sc  = (tid & 15) << 2;     // 0..60 : col within tile row
    const int n0  = j0 << 2;

    for (int kb = 0; kb < K; kb += KB) {
        int kg = kb + skk;
        const float* ap = (kg < A0k) ? (A0 + (size_t)kg * BB)
                                     : (A1 + (size_t)(kg - A0k) * BB);
        float4 av = __ldcg((const float4*)(ap + m0 + sc));
        float4 wv = __ldg((const float4*)(Wp + (size_t)kg * G4 + n0 + sc));
        __syncthreads();                 // previous chunk's compute done
        *(float4*)(As2 + skk * 128 + (sc << 1))     = make_float4(av.x, av.x, av.y, av.y);
        *(float4*)(As2 + skk * 128 + (sc << 1) + 4) = make_float4(av.z, av.z, av.w, av.w);
        *(float4*)(Ws + skk * 64 + sc) = wv;
        __syncthreads();
#pragma unroll
        for (int kk = 0; kk < KB; kk++) {
            ulonglong2 w  = *(const ulonglong2*)(Ws  + kk * 64  + (tc << 2));
            ulonglong2 a0 = *(const ulonglong2*)(As2 + kk * 128 + (rloc << 1));
            ulonglong2 a1 = *(const ulonglong2*)(As2 + kk * 128 + (rloc << 1) + 4);
            FFMA2(acc[0][0], a0.x, w.x); FFMA2(acc[0][1], a0.x, w.y);
            FFMA2(acc[1][0], a0.y, w.x); FFMA2(acc[1][1], a0.y, w.y);
            FFMA2(acc[2][0], a1.x, w.x); FFMA2(acc[2][1], a1.x, w.y);
            FFMA2(acc[3][0], a1.y, w.x); FFMA2(acc[3][1], a1.y, w.y);
        }
    }

    // unpack: acc[r][0] = (gate_i, gate_f), acc[r][1] = (gate_g, gate_o)
    float gi[4], gf[4], gg_[4], go[4];
#pragma unroll
    for (int r = 0; r < 4; r++) {
        float2 p0 = unpack2(acc[r][0]);
        float2 p1 = unpack2(acc[r][1]);
        gi[r] = p0.x; gf[r] = p0.y; gg_[r] = p1.x; go[r] = p1.y;
    }

    const int jg = j0 + tc;
    if (wxp) {  // decoder layer0: gates += x[m] * wx[n]
        float4 w = *(const float4*)(wxp + (jg << 2));
        const float* xp = xvec + m0 + rloc;
#pragma unroll
        for (int r = 0; r < 4; r++) {
            float x = __ldcg(xp + r);
            gi[r]  += x * w.x; gf[r] += x * w.y;
            gg_[r] += x * w.z; go[r] += x * w.w;
        }
    }

    float4 b = *(const float4*)(bias + (jg << 2));
    float* cp = cT + (size_t)jg * BB + m0 + rloc;
    float4 cv = __ldcg((const float4*)cp);
    float cin[4] = {cv.x, cv.y, cv.z, cv.w};
    float hv[4], cn[4];
#pragma unroll
    for (int r = 0; r < 4; r++) {
        float ig = sigf(gi[r] + b.x);
        float fg = sigf(gf[r] + b.y);
        float gv = tanhf(gg_[r] + b.z);
        float og = sigf(go[r] + b.w);
        cn[r] = fg * cin[r] + ig * gv;
        hv[r] = og * tanhf(cn[r]);
    }
    __stcg((float4*)cp, make_float4(cn[0], cn[1], cn[2], cn[3]));
    __stcg((float4*)(hT_out + (size_t)jg * BB + m0 + rloc),
           make_float4(hv[0], hv[1], hv[2], hv[3]));
}

// fc layer 1: o1[n][m] = relu( relu(h1)[m,:] @ fcW0t[:,n] + b0[n] )
__device__ __forceinline__ void fc1_phase(
    const float* __restrict__ h1,     // [k][m]
    const float* __restrict__ fcb0,
    int m0, int j0, int tid, int tc, int rloc,
    float* As, float* Ws)
{
    float acc[4] = {0.f, 0.f, 0.f, 0.f};
    const int skk = tid >> 4;
    const int sc  = (tid & 15) << 2;
    const int stc = tid & 15;
    for (int kb = 0; kb < HN; kb += KB) {
        int kg = kb + skk;
        float4 av = __ldcg((const float4*)(h1 + (size_t)kg * BB + m0 + sc));
        av.x = fmaxf(av.x, 0.f); av.y = fmaxf(av.y, 0.f);
        av.z = fmaxf(av.z, 0.f); av.w = fmaxf(av.w, 0.f);
        float wv = __ldg(d_fcW0t + (size_t)kg * 512 + j0 + stc);
        __syncthreads();
        *(float4*)(As + skk * 64 + sc) = av;
        Ws[skk * 16 + stc] = wv;
        __syncthreads();
#pragma unroll
        for (int kk = 0; kk < KB; kk++) {
            float4 a = *(float4*)(As + kk * 64 + rloc);
            float  w = Ws[kk * 16 + tc];
            acc[0] += a.x * w; acc[1] += a.y * w; acc[2] += a.z * w; acc[3] += a.w * w;
        }
    }
    float bb = __ldg(fcb0 + j0 + tc);
    float4 o;
    o.x = fmaxf(acc[0] + bb, 0.f);
    o.y = fmaxf(acc[1] + bb, 0.f);
    o.z = fmaxf(acc[2] + bb, 0.f);
    o.w = fmaxf(acc[3] + bb, 0.f);
    __stcg((float4*)(d_o1T + (size_t)(j0 + tc) * BB + m0 + rloc), o);
}

// fc layer 2 + output + feedback: out2[m] = o1[m,:] @ fcW1 + b1
__device__ __forceinline__ void fc2_phase(
    const float* __restrict__ fcW1, const float* __restrict__ fcb1,
    float* __restrict__ out, int t, int cta, int tid)
{
    if (cta < 32) {
        int w = tid >> 5;         // warp 0..7
        int lane = tid & 31;
        int m = cta * 8 + w;
        float s = 0.f;
#pragma unroll
        for (int q = 0; q < 16; q++) {
            int k = lane + (q << 5);
            s += __ldcg(d_o1T + (size_t)k * BB + m) * __ldg(fcW1 + k);
        }
#pragma unroll
        for (int off = 16; off; off >>= 1) s += __shfl_down_sync(0xffffffffu, s, off);
        if (lane == 0) {
            float r = s + __ldg(fcb1);
            out[m * TDEC + t] = r;
            __stcg(d_xdec + m, r);
        }
    }
}

// Grid barrier: monotonic generation, state reset to 0 by pack_misc before this
// kernel each launch. Race-free: an arrival at barrier b can only happen after
// all NCTA arrivals at b-1, so the count for barrier b is exactly (b-1)*NCTA+1
// .. b*NCTA, and exactly one CTA observes a == b*NCTA.
#define GBAR() do {                                                         \
    __syncthreads();                                                        \
    if (tid == 0) {                                                         \
        bcnt++;                                                             \
        __threadfence();                                                    \
        unsigned a = atomicAdd(&g_arrive, 1u) + 1u;                         \
        if (a == bcnt * (unsigned)NCTA) {                                   \
            __threadfence();                                                \
            atomicExch(&g_gen, bcnt);                                       \
        } else {                                                            \
            while (*(volatile unsigned*)&g_gen < bcnt) {                    \
                __nanosleep(32);                                            \
            }                                                               \
            __threadfence();                                                \
        }                                                                   \
    }                                                                       \
    __syncthreads();                                                        \
} while (0)

__global__ void __launch_bounds__(NTHR, 1)
lstm_main(const float* __restrict__ fcb0, const float* __restrict__ fcW1,
          const float* __restrict__ fcb1, float* __restrict__ out)
{
    __shared__ __align__(16) float As2[KB * 128];   // duplicated-pair A staging
    __shared__ __align__(16) float Ws[KB * 64];

    const int tid = threadIdx.x;
    unsigned bcnt = 0;

    const int cta = blockIdx.x;
    const int mi = cta & 3, ji = cta >> 2;
    const int m0 = mi * 64, j0 = ji * 16;
    const int tc = tid & 15;
    const int rloc = (tid >> 4) << 2;

    int cur = 0;
    // -------- encoder: 512 steps, 1 grid barrier per step --------
    for (int t = 0; t < TENC; t++) {
        lstm_phase(d_srcT + (size_t)t * 64 * BB, 64, d_h0T[cur], HN,
                   d_encW0p, d_be0, 0, 0,
                   d_c0T, d_h0T[cur ^ 1], m0, j0, tid, tc, rloc, As2, Ws);
        GBAR();
        lstm_phase(d_h0T[cur ^ 1], HN, d_h1T[cur], HN,
                   d_encW1p, d_be1, 0, 0,
                   d_c1T, d_h1T[cur ^ 1], m0, j0, tid, tc, rloc, As2, Ws);
        cur ^= 1;
        // no barrier needed here: next phase-A neither reads h1 nor writes
        // anything phase-B reads; double-buffered h covers the skew window.
    }
    // -------- decoder: 96 steps, 4 barriers per step --------
    for (int t = 0; t < TDEC; t++) {
        lstm_phase(0, 0, d_h0T[cur], HN,
                   d_decW0p, d_bd0, d_xdec, d_wx0,
                   d_c0T, d_h0T[cur ^ 1], m0, j0, tid, tc, rloc, As2, Ws);
        GBAR();
        lstm_phase(d_h0T[cur ^ 1], HN, d_h1T[cur], HN,
                   d_decW1p, d_bd1, 0, 0,
                   d_c1T, d_h1T[cur ^ 1], m0, j0, tid, tc, rloc, As2, Ws);
        GBAR();
        fc1_phase(d_h1T[cur ^ 1], fcb0, m0, j0, tid, tc, rloc, As2, Ws);
        GBAR();
        fc2_phase(fcW1, fcb1, out, t, cta, tid);
        GBAR();
        cur ^= 1;
    }
}

// ---------------- launch ----------------
extern "C" void kernel_launch(void* const* d_in, const int* in_sizes, int n_in,
                              void* d_out, int out_size)
{
    (void)in_sizes; (void)n_in; (void)out_size;
    const float* src  = (const float*)d_in[0];
    const float* tgt  = (const float*)d_in[1];
    const float* eWi0 = (const float*)d_in[2];
    const float* eWh0 = (const float*)d_in[3];
    const float* ebi0 = (const float*)d_in[4];
    const float* ebh0 = (const float*)d_in[5];
    const float* dWi0 = (const float*)d_in[6];
    const float* dWh0 = (const float*)d_in[7];
    const float* dbi0 = (const float*)d_in[8];
    const float* dbh0 = (const float*)d_in[9];
    const float* eWi1 = (const float*)d_in[10];
    const float* eWh1 = (const float*)d_in[11];
    const float* ebi1 = (const float*)d_in[12];
    const float* ebh1 = (const float*)d_in[13];
    const float* dWi1 = (const float*)d_in[14];
    const float* dWh1 = (const float*)d_in[15];
    const float* dbi1 = (const float*)d_in[16];
    const float* dbh1 = (const float*)d_in[17];
    const float* fcW0 = (const float*)d_in[18];
    const float* fcb0 = (const float*)d_in[19];
    const float* fcW1 = (const float*)d_in[20];
    const float* fcb1 = (const float*)d_in[21];

    pack_lstm<<<512, 256>>>(eWi0, eWh0, ebi0, ebh0, 64, 0);
    pack_lstm<<<512, 256>>>(eWi1, eWh1, ebi1, ebh1, 512, 1);
    pack_lstm<<<512, 256>>>(dWh0, dWh0, dbi0, dbh0, 0, 2);   // kin=0: Wih unused
    pack_lstm<<<512, 256>>>(dWi1, dWh1, dbi1, dbh1, 512, 3);
    pack_misc<<<4096, 256>>>(src, tgt, dWi0, fcW0);
    lstm_main<<<NCTA, NTHR>>>(fcb0, fcW1, fcb1, (float*)d_out);
}

// round 3
// speedup vs baseline: 1.1808x; 1.1808x over previous
#include <cuda_runtime.h>

// ---------------- problem constants ----------------
#define HN   512      // hidden
#define BB   256      // batch
#define G4   2048     // 4*H
#define TENC 512
#define TDEC 96
#define NCTA 128
#define NTHR 256
#define KB   16       // K-chunk

// packed f32x2 FMA (SASS FFMA2) — PTX-only pattern
#define FFMA2(d, a, b) \
    asm("fma.rn.f32x2 %0, %1, %2, %0;" : "+l"(d) : "l"(a), "l"(b))

__device__ __forceinline__ float2 unpack2(unsigned long long v) {
    float2 r;
    asm("mov.b64 {%0, %1}, %2;" : "=f"(r.x), "=f"(r.y) : "l"(v));
    return r;
}

// ---------------- device scratch (static: allocation rules) ----------------
__device__ __align__(16) float d_encW0p[576 * G4];
__device__ __align__(16) float d_encW1p[1024 * G4];
__device__ __align__(16) float d_decW0p[512 * G4];
__device__ __align__(16) float d_decW1p[1024 * G4];
__device__ __align__(16) float d_wx0[G4];
__device__ __align__(16) float d_be0[G4];
__device__ __align__(16) float d_be1[G4];
__device__ __align__(16) float d_bd0[G4];
__device__ __align__(16) float d_bd1[G4];
__device__ __align__(16) float d_fcW0t[512 * 512];
__device__ __align__(16) float d_srcT[TENC * 64 * BB];     // [t*64+k][m]
__device__ __align__(16) float d_h0T[2][HN * BB];          // [k][m], double buffered
__device__ __align__(16) float d_h1T[2][HN * BB];
__device__ __align__(16) float d_c0T[HN * BB];
__device__ __align__(16) float d_c1T[HN * BB];
__device__ __align__(16) float d_o1T[HN * BB];             // fc hidden, [n][m]
__device__ __align__(16) float d_xdec[BB];
__device__ unsigned g_gen;     // barrier generation (reset each launch by pack_misc)
__device__ unsigned g_arrive;  // arrival counter    (reset each launch by pack_misc)

// ---------------- packing kernels ----------------
__global__ void pack_lstm(const float* __restrict__ Wih, const float* __restrict__ Whh,
                          const float* __restrict__ bih, const float* __restrict__ bhh,
                          int kin, int sel)
{
    float* Wp = (sel == 0) ? d_encW0p : (sel == 1) ? d_encW1p : (sel == 2) ? d_decW0p : d_decW1p;
    float* bs = (sel == 0) ? d_be0    : (sel == 1) ? d_be1    : (sel == 2) ? d_bd0    : d_bd1;
    int K = kin + HN;
    int total = K * G4;
    for (int idx = blockIdx.x * blockDim.x + threadIdx.x; idx < total;
         idx += gridDim.x * blockDim.x) {
        int k = idx >> 11;          // /2048
        int n = idx & 2047;
        int j = n >> 2, g = n & 3;
        int row = g * HN + j;
        float v = (k < kin) ? Wih[(long long)row * kin + k]
                            : Whh[(long long)row * HN + (k - kin)];
        Wp[idx] = v;
    }
    int t = blockIdx.x * blockDim.x + threadIdx.x;
    if (t < G4) {
        int j = t >> 2, g = t & 3;
        int row = g * HN + j;
        bs[t] = bih[row] + bhh[row];
    }
}

__global__ void pack_misc(const float* __restrict__ src, const float* __restrict__ tgt,
                          const float* __restrict__ decWih0, const float* __restrict__ fcW0)
{
    // reset grid-barrier state every launch (stream-ordered before lstm_main)
    if (blockIdx.x == 0 && threadIdx.x == 0) { g_gen = 0u; g_arrive = 0u; }

    const long long N_SRC = (long long)TENC * 64 * BB;   // 8388608
    const long long N_FC  = 512 * 512;                   // 262144
    const long long N_WX  = G4;                          // 2048
    const long long N_Z   = 6LL * HN * BB;               // 786432
    const long long TOTAL = N_SRC + N_FC + N_WX + N_Z + BB;
    for (long long idx = (long long)blockIdx.x * blockDim.x + threadIdx.x; idx < TOTAL;
         idx += (long long)gridDim.x * blockDim.x) {
        long long i = idx;
        if (i < N_SRC) {
            int tk = (int)(i >> 8);
            int m  = (int)(i & 255);
            d_srcT[i] = src[(long long)m * (TENC * 64) + tk];
            continue;
        }
        i -= N_SRC;
        if (i < N_FC) {      // d_fcW0t[k*512+n] = fcW0[n*512+k]
            int n = (int)(i & 511);
            int k = (int)(i >> 9);
            d_fcW0t[i] = fcW0[n * 512 + k];
            continue;
        }
        i -= N_FC;
        if (i < N_WX) {      // d_wx0[j*4+g] = dec_Wih0[g*512+j]  ([2048][1])
            int j = (int)(i >> 2), g = (int)(i & 3);
            d_wx0[i] = decWih0[g * HN + j];
            continue;
        }
        i -= N_WX;
        if (i < N_Z) {
            int which = (int)(i / (HN * BB));
            int off   = (int)(i % (HN * BB));
            float* p = (which == 0) ? d_h0T[0] : (which == 1) ? d_h0T[1] :
                       (which == 2) ? d_h1T[0] : (which == 3) ? d_h1T[1] :
                       (which == 4) ? d_c0T    : d_c1T;
            p[off] = 0.f;
            continue;
        }
        i -= N_Z;
        d_xdec[i] = tgt[i * TDEC];   // tgt[:,0]
    }
}

// ---------------- main persistent kernel ----------------
__device__ __forceinline__ float sigf(float x) { return 1.f / (1.f + expf(-x)); }

// One LSTM layer-step for this CTA's tile, software-pipelined:
//   gates = [A0 | A1] @ Wp + bias (+ x*wx) -> cell -> hT_out, cT
// A0/A1 are k-major [K][256]. Tile: rows m0..m0+63, hidden j0..j0+15 (4 gates).
// Double-buffered smem staging, register prefetch 2 chunks ahead, ONE
// __syncthreads per chunk. Inner product uses packed f32x2 FMA (FFMA2):
// A duplicated pairwise in shared so both operands come from LDS.128.
__device__ __forceinline__ void lstm_phase(
    const float* __restrict__ A0, int A0k,
    const float* __restrict__ A1, int A1k,
    const float* __restrict__ Wp,
    const float* __restrict__ bias,
    const float* __restrict__ xvec, const float* __restrict__ wxp,
    float* __restrict__ cT, float* __restrict__ hT_out,
    int m0, int j0, int tid, int tc, int rloc,
    float* As2, float* Ws)      // As2: 2*KB*128, Ws: 2*KB*64
{
    unsigned long long acc[4][2];
#pragma unroll
    for (int r = 0; r < 4; r++) { acc[r][0] = 0ull; acc[r][1] = 0ull; }

    const int K = A0k + A1k;
    const int nch = K >> 4;              // K / KB
    const int skk = tid >> 4;            // 0..15 : k within chunk
    const int sc  = (tid & 15) << 2;     // 0..60 : col within tile row
    const int n0  = j0 << 2;
    const int sA  = skk * 128 + (sc << 1);   // A-store offset within buffer
    const int sW  = skk * 64 + sc;
    const int rA  = rloc << 1;               // A-read base
    const int rW  = tc << 2;

    // ---- prologue: load chunk 0, stage to buf 0, prefetch chunk 1 ----
    float4 av, wv;
    {
        int kg = skk;
        const float* ap = (kg < A0k) ? (A0 + (size_t)kg * BB)
                                     : (A1 + (size_t)(kg - A0k) * BB);
        av = __ldcg((const float4*)(ap + m0 + sc));
        wv = __ldg((const float4*)(Wp + (size_t)kg * G4 + n0 + sc));
    }
    __syncthreads();   // previous phase's smem readers done
    *(float4*)(As2 + sA)     = make_float4(av.x, av.x, av.y, av.y);
    *(float4*)(As2 + sA + 4) = make_float4(av.z, av.z, av.w, av.w);
    *(float4*)(Ws + sW)      = wv;
    if (nch > 1) {
        int kg = KB + skk;
        const float* ap = (kg < A0k) ? (A0 + (size_t)kg * BB)
                                     : (A1 + (size_t)(kg - A0k) * BB);
        av = __ldcg((const float4*)(ap + m0 + sc));
        wv = __ldg((const float4*)(Wp + (size_t)kg * G4 + n0 + sc));
    }

    // ---- main pipelined loop: one sync per chunk ----
    for (int i = 0; i < nch; i++) {
        __syncthreads();   // buf[i&1] staged & visible; compute(i-1) done everywhere
        if (i + 1 < nch) {
            float* a2 = As2 + (((i + 1) & 1) ? KB * 128 : 0);
            float* w2 = Ws  + (((i + 1) & 1) ? KB * 64  : 0);
            *(float4*)(a2 + sA)     = make_float4(av.x, av.x, av.y, av.y);
            *(float4*)(a2 + sA + 4) = make_float4(av.z, av.z, av.w, av.w);
            *(float4*)(w2 + sW)     = wv;
        }
        if (i + 2 < nch) {   // prefetch 2 ahead; latency hidden by compute below
            int kg = (i + 2) * KB + skk;
            const float* ap = (kg < A0k) ? (A0 + (size_t)kg * BB)
                                         : (A1 + (size_t)(kg - A0k) * BB);
            av = __ldcg((const float4*)(ap + m0 + sc));
            wv = __ldg((const float4*)(Wp + (size_t)kg * G4 + n0 + sc));
        }
        const float* ab = As2 + ((i & 1) ? KB * 128 : 0);
        const float* wb = Ws  + ((i & 1) ? KB * 64  : 0);
#pragma unroll
        for (int kk = 0; kk < KB; kk++) {
            ulonglong2 w  = *(const ulonglong2*)(wb + kk * 64  + rW);
            ulonglong2 a0 = *(const ulonglong2*)(ab + kk * 128 + rA);
            ulonglong2 a1 = *(const ulonglong2*)(ab + kk * 128 + rA + 4);
            FFMA2(acc[0][0], a0.x, w.x); FFMA2(acc[0][1], a0.x, w.y);
            FFMA2(acc[1][0], a0.y, w.x); FFMA2(acc[1][1], a0.y, w.y);
            FFMA2(acc[2][0], a1.x, w.x); FFMA2(acc[2][1], a1.x, w.y);
            FFMA2(acc[3][0], a1.y, w.x); FFMA2(acc[3][1], a1.y, w.y);
        }
    }

    // unpack: acc[r][0] = (gate_i, gate_f), acc[r][1] = (gate_g, gate_o)
    float gi[4], gf[4], gg_[4], go[4];
#pragma unroll
    for (int r = 0; r < 4; r++) {
        float2 p0 = unpack2(acc[r][0]);
        float2 p1 = unpack2(acc[r][1]);
        gi[r] = p0.x; gf[r] = p0.y; gg_[r] = p1.x; go[r] = p1.y;
    }

    const int jg = j0 + tc;
    if (wxp) {  // decoder layer0: gates += x[m] * wx[n]
        float4 w = *(const float4*)(wxp + (jg << 2));
        const float* xp = xvec + m0 + rloc;
#pragma unroll
        for (int r = 0; r < 4; r++) {
            float x = __ldcg(xp + r);
            gi[r]  += x * w.x; gf[r] += x * w.y;
            gg_[r] += x * w.z; go[r] += x * w.w;
        }
    }

    float4 b = *(const float4*)(bias + (jg << 2));
    float* cp = cT + (size_t)jg * BB + m0 + rloc;
    float4 cv = __ldcg((const float4*)cp);
    float cin[4] = {cv.x, cv.y, cv.z, cv.w};
    float hv[4], cn[4];
#pragma unroll
    for (int r = 0; r < 4; r++) {
        float ig = sigf(gi[r] + b.x);
        float fg = sigf(gf[r] + b.y);
        float gv = tanhf(gg_[r] + b.z);
        float og = sigf(go[r] + b.w);
        cn[r] = fg * cin[r] + ig * gv;
        hv[r] = og * tanhf(cn[r]);
    }
    __stcg((float4*)cp, make_float4(cn[0], cn[1], cn[2], cn[3]));
    __stcg((float4*)(hT_out + (size_t)jg * BB + m0 + rloc),
           make_float4(hv[0], hv[1], hv[2], hv[3]));
}

// fc layer 1: o1[n][m] = relu( relu(h1)[m,:] @ fcW0t[:,n] + b0[n] )
__device__ __forceinline__ void fc1_phase(
    const float* __restrict__ h1,     // [k][m]
    const float* __restrict__ fcb0,
    int m0, int j0, int tid, int tc, int rloc,
    float* As, float* Ws)
{
    float acc[4] = {0.f, 0.f, 0.f, 0.f};
    const int skk = tid >> 4;
    const int sc  = (tid & 15) << 2;
    const int stc = tid & 15;
    for (int kb = 0; kb < HN; kb += KB) {
        int kg = kb + skk;
        float4 av = __ldcg((const float4*)(h1 + (size_t)kg * BB + m0 + sc));
        av.x = fmaxf(av.x, 0.f); av.y = fmaxf(av.y, 0.f);
        av.z = fmaxf(av.z, 0.f); av.w = fmaxf(av.w, 0.f);
        float wv = __ldg(d_fcW0t + (size_t)kg * 512 + j0 + stc);
        __syncthreads();
        *(float4*)(As + skk * 64 + sc) = av;
        Ws[skk * 16 + stc] = wv;
        __syncthreads();
#pragma unroll
        for (int kk = 0; kk < KB; kk++) {
            float4 a = *(float4*)(As + kk * 64 + rloc);
            float  w = Ws[kk * 16 + tc];
            acc[0] += a.x * w; acc[1] += a.y * w; acc[2] += a.z * w; acc[3] += a.w * w;
        }
    }
    float bb = __ldg(fcb0 + j0 + tc);
    float4 o;
    o.x = fmaxf(acc[0] + bb, 0.f);
    o.y = fmaxf(acc[1] + bb, 0.f);
    o.z = fmaxf(acc[2] + bb, 0.f);
    o.w = fmaxf(acc[3] + bb, 0.f);
    __stcg((float4*)(d_o1T + (size_t)(j0 + tc) * BB + m0 + rloc), o);
}

// fc layer 2 + output + feedback: out2[m] = o1[m,:] @ fcW1 + b1
__device__ __forceinline__ void fc2_phase(
    const float* __restrict__ fcW1, const float* __restrict__ fcb1,
    float* __restrict__ out, int t, int cta, int tid)
{
    if (cta < 32) {
        int w = tid >> 5;         // warp 0..7
        int lane = tid & 31;
        int m = cta * 8 + w;
        float s = 0.f;
#pragma unroll
        for (int q = 0; q < 16; q++) {
            int k = lane + (q << 5);
            s += __ldcg(d_o1T + (size_t)k * BB + m) * __ldg(fcW1 + k);
        }
#pragma unroll
        for (int off = 16; off; off >>= 1) s += __shfl_down_sync(0xffffffffu, s, off);
        if (lane == 0) {
            float r = s + __ldg(fcb1);
            out[m * TDEC + t] = r;
            __stcg(d_xdec + m, r);
        }
    }
}

// Grid barrier: monotonic generation, state reset to 0 by pack_misc before this
// kernel each launch. Race-free: an arrival at barrier b can only happen after
// all NCTA arrivals at b-1.
#define GBAR() do {                                                         \
    __syncthreads();                                                        \
    if (tid == 0) {                                                         \
        bcnt++;                                                             \
        __threadfence();                                                    \
        unsigned a = atomicAdd(&g_arrive, 1u) + 1u;                         \
        if (a == bcnt * (unsigned)NCTA) {                                   \
            __threadfence();                                                \
            atomicExch(&g_gen, bcnt);                                       \
        } else {                                                            \
            while (*(volatile unsigned*)&g_gen < bcnt) {                    \
                __nanosleep(16);                                            \
            }                                                               \
            __threadfence();                                                \
        }                                                                   \
    }                                                                       \
    __syncthreads();                                                        \
} while (0)

__global__ void __launch_bounds__(NTHR, 1)
lstm_main(const float* __restrict__ fcb0, const float* __restrict__ fcW1,
          const float* __restrict__ fcb1, float* __restrict__ out)
{
    __shared__ __align__(16) float As2[2 * KB * 128];   // double-buffered A (dup pairs)
    __shared__ __align__(16) float Ws[2 * KB * 64];     // double-buffered W

    const int tid = threadIdx.x;
    unsigned bcnt = 0;

    const int cta = blockIdx.x;
    const int mi = cta & 3, ji = cta >> 2;
    const int m0 = mi * 64, j0 = ji * 16;
    const int tc = tid & 15;
    const int rloc = (tid >> 4) << 2;

    int cur = 0;
    // -------- encoder: 512 steps, 1 grid barrier per step --------
    for (int t = 0; t < TENC; t++) {
        lstm_phase(d_srcT + (size_t)t * 64 * BB, 64, d_h0T[cur], HN,
                   d_encW0p, d_be0, 0, 0,
                   d_c0T, d_h0T[cur ^ 1], m0, j0, tid, tc, rloc, As2, Ws);
        GBAR();
        lstm_phase(d_h0T[cur ^ 1], HN, d_h1T[cur], HN,
                   d_encW1p, d_be1, 0, 0,
                   d_c1T, d_h1T[cur ^ 1], m0, j0, tid, tc, rloc, As2, Ws);
        cur ^= 1;
        // no barrier needed here: next phase-A neither reads h1 nor writes
        // anything phase-B reads; double-buffered h covers the skew window.
    }
    // -------- decoder: 96 steps, 4 barriers per step --------
    for (int t = 0; t < TDEC; t++) {
        lstm_phase(0, 0, d_h0T[cur], HN,
                   d_decW0p, d_bd0, d_xdec, d_wx0,
                   d_c0T, d_h0T[cur ^ 1], m0, j0, tid, tc, rloc, As2, Ws);
        GBAR();
        lstm_phase(d_h0T[cur ^ 1], HN, d_h1T[cur], HN,
                   d_decW1p, d_bd1, 0, 0,
                   d_c1T, d_h1T[cur ^ 1], m0, j0, tid, tc, rloc, As2, Ws);
        GBAR();
        fc1_phase(d_h1T[cur ^ 1], fcb0, m0, j0, tid, tc, rloc, As2, Ws);
        GBAR();
        fc2_phase(fcW1, fcb1, out, t, cta, tid);
        GBAR();
        cur ^= 1;
    }
}

// ---------------- launch ----------------
extern "C" void kernel_launch(void* const* d_in, const int* in_sizes, int n_in,
                              void* d_out, int out_size)
{
    (void)in_sizes; (void)n_in; (void)out_size;
    const float* src  = (const float*)d_in[0];
    const float* tgt  = (const float*)d_in[1];
    const float* eWi0 = (const float*)d_in[2];
    const float* eWh0 = (const float*)d_in[3];
    const float* ebi0 = (const float*)d_in[4];
    const float* ebh0 = (const float*)d_in[5];
    const float* dWi0 = (const float*)d_in[6];
    const float* dWh0 = (const float*)d_in[7];
    const float* dbi0 = (const float*)d_in[8];
    const float* dbh0 = (const float*)d_in[9];
    const float* eWi1 = (const float*)d_in[10];
    const float* eWh1 = (const float*)d_in[11];
    const float* ebi1 = (const float*)d_in[12];
    const float* ebh1 = (const float*)d_in[13];
    const float* dWi1 = (const float*)d_in[14];
    const float* dWh1 = (const float*)d_in[15];
    const float* dbi1 = (const float*)d_in[16];
    const float* dbh1 = (const float*)d_in[17];
    const float* fcW0 = (const float*)d_in[18];
    const float* fcb0 = (const float*)d_in[19];
    const float* fcW1 = (const float*)d_in[20];
    const float* fcb1 = (const float*)d_in[21];

    pack_lstm<<<512, 256>>>(eWi0, eWh0, ebi0, ebh0, 64, 0);
    pack_lstm<<<512, 256>>>(eWi1, eWh1, ebi1, ebh1, 512, 1);
    pack_lstm<<<512, 256>>>(dWh0, dWh0, dbi0, dbh0, 0, 2);   // kin=0: Wih unused
    pack_lstm<<<512, 256>>>(dWi1, dWh1, dbi1, dbh1, 512, 3);
    pack_misc<<<4096, 256>>>(src, tgt, dWi0, fcW0);
    lstm_main<<<NCTA, NTHR>>>(fcb0, fcW1, fcb1, (float*)d_out);
}

// round 4
// speedup vs baseline: 1.1828x; 1.0016x over previous
#include <cuda_runtime.h>

// ---------------- problem constants ----------------
#define HN   512      // hidden
#define BB   256      // batch
#define G4   2048     // 4*H
#define TENC 512
#define TDEC 96
#define NCTA 128
#define NTHR 256
#define KB   16       // K-chunk

// packed f32x2 FMA (SASS FFMA2) — PTX-only pattern
#define FFMA2(d, a, b) \
    asm("fma.rn.f32x2 %0, %1, %2, %0;" : "+l"(d) : "l"(a), "l"(b))

__device__ __forceinline__ float2 unpack2(unsigned long long v) {
    float2 r;
    asm("mov.b64 {%0, %1}, %2;" : "=f"(r.x), "=f"(r.y) : "l"(v));
    return r;
}

// ---------------- device scratch (static: allocation rules) ----------------
__device__ __align__(16) float d_encW0p[576 * G4];
__device__ __align__(16) float d_encW1p[1024 * G4];
__device__ __align__(16) float d_decW0p[512 * G4];
__device__ __align__(16) float d_decW1p[1024 * G4];
__device__ __align__(16) float d_wx0[G4];
__device__ __align__(16) float d_be0[G4];
__device__ __align__(16) float d_be1[G4];
__device__ __align__(16) float d_bd0[G4];
__device__ __align__(16) float d_bd1[G4];
__device__ __align__(16) float d_fcW0t[512 * 512];
__device__ __align__(16) float d_srcT[TENC * 64 * BB];     // [t*64+k][m]
__device__ __align__(16) float d_h0T[2][HN * BB];          // [k][m], double buffered
__device__ __align__(16) float d_h1T[2][HN * BB];
__device__ __align__(16) float d_c0T[HN * BB];
__device__ __align__(16) float d_c1T[HN * BB];
__device__ __align__(16) float d_o1T[HN * BB];             // fc hidden, [n][m]
__device__ __align__(16) float d_xdec[BB];
__device__ unsigned g_gen;     // barrier generation (reset each launch by pack_misc)
__device__ unsigned g_arrive;  // arrival counter    (reset each launch by pack_misc)

// ---------------- packing kernels ----------------
__global__ void pack_lstm(const float* __restrict__ Wih, const float* __restrict__ Whh,
                          const float* __restrict__ bih, const float* __restrict__ bhh,
                          int kin, int sel)
{
    float* Wp = (sel == 0) ? d_encW0p : (sel == 1) ? d_encW1p : (sel == 2) ? d_decW0p : d_decW1p;
    float* bs = (sel == 0) ? d_be0    : (sel == 1) ? d_be1    : (sel == 2) ? d_bd0    : d_bd1;
    int K = kin + HN;
    int total = K * G4;
    for (int idx = blockIdx.x * blockDim.x + threadIdx.x; idx < total;
         idx += gridDim.x * blockDim.x) {
        int k = idx >> 11;          // /2048
        int n = idx & 2047;
        int j = n >> 2, g = n & 3;
        int row = g * HN + j;
        float v = (k < kin) ? Wih[(long long)row * kin + k]
                            : Whh[(long long)row * HN + (k - kin)];
        Wp[idx] = v;
    }
    int t = blockIdx.x * blockDim.x + threadIdx.x;
    if (t < G4) {
        int j = t >> 2, g = t & 3;
        int row = g * HN + j;
        bs[t] = bih[row] + bhh[row];
    }
}

__global__ void pack_misc(const float* __restrict__ src, const float* __restrict__ tgt,
                          const float* __restrict__ decWih0, const float* __restrict__ fcW0)
{
    // reset grid-barrier state every launch (stream-ordered before lstm_main)
    if (blockIdx.x == 0 && threadIdx.x == 0) { g_gen = 0u; g_arrive = 0u; }

    const long long N_SRC = (long long)TENC * 64 * BB;   // 8388608
    const long long N_FC  = 512 * 512;                   // 262144
    const long long N_WX  = G4;                          // 2048
    const long long N_Z   = 6LL * HN * BB;               // 786432
    const long long TOTAL = N_SRC + N_FC + N_WX + N_Z + BB;
    for (long long idx = (long long)blockIdx.x * blockDim.x + threadIdx.x; idx < TOTAL;
         idx += (long long)gridDim.x * blockDim.x) {
        long long i = idx;
        if (i < N_SRC) {
            int tk = (int)(i >> 8);
            int m  = (int)(i & 255);
            d_srcT[i] = src[(long long)m * (TENC * 64) + tk];
            continue;
        }
        i -= N_SRC;
        if (i < N_FC) {      // d_fcW0t[k*512+n] = fcW0[n*512+k]
            int n = (int)(i & 511);
            int k = (int)(i >> 9);
            d_fcW0t[i] = fcW0[n * 512 + k];
            continue;
        }
        i -= N_FC;
        if (i < N_WX) {      // d_wx0[j*4+g] = dec_Wih0[g*512+j]  ([2048][1])
            int j = (int)(i >> 2), g = (int)(i & 3);
            d_wx0[i] = decWih0[g * HN + j];
            continue;
        }
        i -= N_WX;
        if (i < N_Z) {
            int which = (int)(i / (HN * BB));
            int off   = (int)(i % (HN * BB));
            float* p = (which == 0) ? d_h0T[0] : (which == 1) ? d_h0T[1] :
                       (which == 2) ? d_h1T[0] : (which == 3) ? d_h1T[1] :
                       (which == 4) ? d_c0T    : d_c1T;
            p[off] = 0.f;
            continue;
        }
        i -= N_Z;
        d_xdec[i] = tgt[i * TDEC];   // tgt[:,0]
    }
}

// ---------------- main persistent kernel ----------------
__device__ __forceinline__ float sigf(float x) { return 1.f / (1.f + expf(-x)); }

// One LSTM layer-step for this CTA's tile, software-pipelined:
//   gates = [A0 | A1] @ Wp + bias (+ x*wx) -> cell -> hT_out, cT
// A0/A1 are k-major [K][256]. Tile: rows m0..m0+63, hidden j0..j0+15 (4 gates).
// Double-buffered smem staging, register prefetch 2 chunks ahead, ONE
// __syncthreads per chunk. Inner product uses packed f32x2 FMA (FFMA2):
// A duplicated pairwise in shared so both operands come from LDS.128.
__device__ __forceinline__ void lstm_phase(
    const float* __restrict__ A0, int A0k,
    const float* __restrict__ A1, int A1k,
    const float* __restrict__ Wp,
    const float* __restrict__ bias,
    const float* __restrict__ xvec, const float* __restrict__ wxp,
    float* __restrict__ cT, float* __restrict__ hT_out,
    int m0, int j0, int tid, int tc, int rloc,
    float* As2, float* Ws)      // As2: 2*KB*128, Ws: 2*KB*64
{
    unsigned long long acc[4][2];
#pragma unroll
    for (int r = 0; r < 4; r++) { acc[r][0] = 0ull; acc[r][1] = 0ull; }

    const int K = A0k + A1k;
    const int nch = K >> 4;              // K / KB
    const int skk = tid >> 4;            // 0..15 : k within chunk
    const int sc  = (tid & 15) << 2;     // 0..60 : col within tile row
    const int n0  = j0 << 2;
    const int sA  = skk * 128 + (sc << 1);   // A-store offset within buffer
    const int sW  = skk * 64 + sc;
    const int rA  = rloc << 1;               // A-read base
    const int rW  = tc << 2;

    // ---- prologue: load chunk 0, stage to buf 0, prefetch chunk 1 ----
    float4 av, wv;
    {
        int kg = skk;
        const float* ap = (kg < A0k) ? (A0 + (size_t)kg * BB)
                                     : (A1 + (size_t)(kg - A0k) * BB);
        av = __ldcg((const float4*)(ap + m0 + sc));
        wv = __ldg((const float4*)(Wp + (size_t)kg * G4 + n0 + sc));
    }
    __syncthreads();   // previous phase's smem readers done
    *(float4*)(As2 + sA)     = make_float4(av.x, av.x, av.y, av.y);
    *(float4*)(As2 + sA + 4) = make_float4(av.z, av.z, av.w, av.w);
    *(float4*)(Ws + sW)      = wv;
    if (nch > 1) {
        int kg = KB + skk;
        const float* ap = (kg < A0k) ? (A0 + (size_t)kg * BB)
                                     : (A1 + (size_t)(kg - A0k) * BB);
        av = __ldcg((const float4*)(ap + m0 + sc));
        wv = __ldg((const float4*)(Wp + (size_t)kg * G4 + n0 + sc));
    }

    // ---- main pipelined loop: one sync per chunk ----
    for (int i = 0; i < nch; i++) {
        __syncthreads();   // buf[i&1] staged & visible; compute(i-1) done everywhere
        if (i + 1 < nch) {
            float* a2 = As2 + (((i + 1) & 1) ? KB * 128 : 0);
            float* w2 = Ws  + (((i + 1) & 1) ? KB * 64  : 0);
            *(float4*)(a2 + sA)     = make_float4(av.x, av.x, av.y, av.y);
            *(float4*)(a2 + sA + 4) = make_float4(av.z, av.z, av.w, av.w);
            *(float4*)(w2 + sW)     = wv;
        }
        if (i + 2 < nch) {   // prefetch 2 ahead; latency hidden by compute below
            int kg = (i + 2) * KB + skk;
            const float* ap = (kg < A0k) ? (A0 + (size_t)kg * BB)
                                         : (A1 + (size_t)(kg - A0k) * BB);
            av = __ldcg((const float4*)(ap + m0 + sc));
            wv = __ldg((const float4*)(Wp + (size_t)kg * G4 + n0 + sc));
        }
        const float* ab = As2 + ((i & 1) ? KB * 128 : 0);
        const float* wb = Ws  + ((i & 1) ? KB * 64  : 0);
#pragma unroll
        for (int kk = 0; kk < KB; kk++) {
            ulonglong2 w  = *(const ulonglong2*)(wb + kk * 64  + rW);
            ulonglong2 a0 = *(const ulonglong2*)(ab + kk * 128 + rA);
            ulonglong2 a1 = *(const ulonglong2*)(ab + kk * 128 + rA + 4);
            FFMA2(acc[0][0], a0.x, w.x); FFMA2(acc[0][1], a0.x, w.y);
            FFMA2(acc[1][0], a0.y, w.x); FFMA2(acc[1][1], a0.y, w.y);
            FFMA2(acc[2][0], a1.x, w.x); FFMA2(acc[2][1], a1.x, w.y);
            FFMA2(acc[3][0], a1.y, w.x); FFMA2(acc[3][1], a1.y, w.y);
        }
    }

    // unpack: acc[r][0] = (gate_i, gate_f), acc[r][1] = (gate_g, gate_o)
    float gi[4], gf[4], gg_[4], go[4];
#pragma unroll
    for (int r = 0; r < 4; r++) {
        float2 p0 = unpack2(acc[r][0]);
        float2 p1 = unpack2(acc[r][1]);
        gi[r] = p0.x; gf[r] = p0.y; gg_[r] = p1.x; go[r] = p1.y;
    }

    const int jg = j0 + tc;
    if (wxp) {  // decoder layer0: gates += x[m] * wx[n]
        float4 w = *(const float4*)(wxp + (jg << 2));
        const float* xp = xvec + m0 + rloc;
#pragma unroll
        for (int r = 0; r < 4; r++) {
            float x = __ldcg(xp + r);
            gi[r]  += x * w.x; gf[r] += x * w.y;
            gg_[r] += x * w.z; go[r] += x * w.w;
        }
    }

    float4 b = *(const float4*)(bias + (jg << 2));
    float* cp = cT + (size_t)jg * BB + m0 + rloc;
    float4 cv = __ldcg((const float4*)cp);
    float cin[4] = {cv.x, cv.y, cv.z, cv.w};
    float hv[4], cn[4];
#pragma unroll
    for (int r = 0; r < 4; r++) {
        float ig = sigf(gi[r] + b.x);
        float fg = sigf(gf[r] + b.y);
        float gv = tanhf(gg_[r] + b.z);
        float og = sigf(go[r] + b.w);
        cn[r] = fg * cin[r] + ig * gv;
        hv[r] = og * tanhf(cn[r]);
    }
    __stcg((float4*)cp, make_float4(cn[0], cn[1], cn[2], cn[3]));
    __stcg((float4*)(hT_out + (size_t)jg * BB + m0 + rloc),
           make_float4(hv[0], hv[1], hv[2], hv[3]));
}

// fc layer 1: o1[n][m] = relu( relu(h1)[m,:] @ fcW0t[:,n] + b0[n] )
__device__ __forceinline__ void fc1_phase(
    const float* __restrict__ h1,     // [k][m]
    const float* __restrict__ fcb0,
    int m0, int j0, int tid, int tc, int rloc,
    float* As, float* Ws)
{
    float acc[4] = {0.f, 0.f, 0.f, 0.f};
    const int skk = tid >> 4;
    const int sc  = (tid & 15) << 2;
    const int stc = tid & 15;
    for (int kb = 0; kb < HN; kb += KB) {
        int kg = kb + skk;
        float4 av = __ldcg((const float4*)(h1 + (size_t)kg * BB + m0 + sc));
        av.x = fmaxf(av.x, 0.f); av.y = fmaxf(av.y, 0.f);
        av.z = fmaxf(av.z, 0.f); av.w = fmaxf(av.w, 0.f);
        float wv = __ldg(d_fcW0t + (size_t)kg * 512 + j0 + stc);
        __syncthreads();
        *(float4*)(As + skk * 64 + sc) = av;
        Ws[skk * 16 + stc] = wv;
        __syncthreads();
#pragma unroll
        for (int kk = 0; kk < KB; kk++) {
            float4 a = *(float4*)(As + kk * 64 + rloc);
            float  w = Ws[kk * 16 + tc];
            acc[0] += a.x * w; acc[1] += a.y * w; acc[2] += a.z * w; acc[3] += a.w * w;
        }
    }
    float bb = __ldg(fcb0 + j0 + tc);
    float4 o;
    o.x = fmaxf(acc[0] + bb, 0.f);
    o.y = fmaxf(acc[1] + bb, 0.f);
    o.z = fmaxf(acc[2] + bb, 0.f);
    o.w = fmaxf(acc[3] + bb, 0.f);
    __stcg((float4*)(d_o1T + (size_t)(j0 + tc) * BB + m0 + rloc), o);
}

// fc layer 2 + output + feedback: out2[m] = o1[m,:] @ fcW1 + b1
__device__ __forceinline__ void fc2_phase(
    const float* __restrict__ fcW1, const float* __restrict__ fcb1,
    float* __restrict__ out, int t, int cta, int tid)
{
    if (cta < 32) {
        int w = tid >> 5;         // warp 0..7
        int lane = tid & 31;
        int m = cta * 8 + w;
        float s = 0.f;
#pragma unroll
        for (int q = 0; q < 16; q++) {
            int k = lane + (q << 5);
            s += __ldcg(d_o1T + (size_t)k * BB + m) * __ldg(fcW1 + k);
        }
#pragma unroll
        for (int off = 16; off; off >>= 1) s += __shfl_down_sync(0xffffffffu, s, off);
        if (lane == 0) {
            float r = s + __ldg(fcb1);
            out[m * TDEC + t] = r;
            __stcg(d_xdec + m, r);
        }
    }
}

// Grid barrier: monotonic generation, state reset to 0 by pack_misc before this
// kernel each launch. Race-free: an arrival at barrier b can only happen after
// all NCTA arrivals at b-1.
#define GBAR() do {                                                         \
    __syncthreads();                                                        \
    if (tid == 0) {                                                         \
        bcnt++;                                                             \
        __threadfence();                                                    \
        unsigned a = atomicAdd(&g_arrive, 1u) + 1u;                         \
        if (a == bcnt * (unsigned)NCTA) {                                   \
            __threadfence();                                                \
            atomicExch(&g_gen, bcnt);                                       \
        } else {                                                            \
            while (*(volatile unsigned*)&g_gen < bcnt) {                    \
                __nanosleep(16);                                            \
            }                                                               \
            __threadfence();                                                \
        }                                                                   \
    }                                                                       \
    __syncthreads();                                                        \
} while (0)

__global__ void __launch_bounds__(NTHR, 1)
lstm_main(const float* __restrict__ fcb0, const float* __restrict__ fcW1,
          const float* __restrict__ fcb1, float* __restrict__ out)
{
    __shared__ __align__(16) float As2[2 * KB * 128];   // double-buffered A (dup pairs)
    __shared__ __align__(16) float Ws[2 * KB * 64];     // double-buffered W

    const int tid = threadIdx.x;
    unsigned bcnt = 0;

    const int cta = blockIdx.x;
    const int mi = cta & 3, ji = cta >> 2;
    const int m0 = mi * 64, j0 = ji * 16;
    const int tc = tid & 15;
    const int rloc = (tid >> 4) << 2;

    int cur = 0;
    // -------- encoder: 512 steps, 1 grid barrier per step --------
    for (int t = 0; t < TENC; t++) {
        lstm_phase(d_srcT + (size_t)t * 64 * BB, 64, d_h0T[cur], HN,
                   d_encW0p, d_be0, 0, 0,
                   d_c0T, d_h0T[cur ^ 1], m0, j0, tid, tc, rloc, As2, Ws);
        GBAR();
        lstm_phase(d_h0T[cur ^ 1], HN, d_h1T[cur], HN,
                   d_encW1p, d_be1, 0, 0,
                   d_c1T, d_h1T[cur ^ 1], m0, j0, tid, tc, rloc, As2, Ws);
        cur ^= 1;
        // no barrier needed here: next phase-A neither reads h1 nor writes
        // anything phase-B reads; double-buffered h covers the skew window.
    }
    // -------- decoder: 96 steps, 4 barriers per step --------
    for (int t = 0; t < TDEC; t++) {
        lstm_phase(0, 0, d_h0T[cur], HN,
                   d_decW0p, d_bd0, d_xdec, d_wx0,
                   d_c0T, d_h0T[cur ^ 1], m0, j0, tid, tc, rloc, As2, Ws);
        GBAR();
        lstm_phase(d_h0T[cur ^ 1], HN, d_h1T[cur], HN,
                   d_decW1p, d_bd1, 0, 0,
                   d_c1T, d_h1T[cur ^ 1], m0, j0, tid, tc, rloc, As2, Ws);
        GBAR();
        fc1_phase(d_h1T[cur ^ 1], fcb0, m0, j0, tid, tc, rloc, As2, Ws);
        GBAR();
        fc2_phase(fcW1, fcb1, out, t, cta, tid);
        GBAR();
        cur ^= 1;
    }
}

// ---------------- launch ----------------
extern "C" void kernel_launch(void* const* d_in, const int* in_sizes, int n_in,
                              void* d_out, int out_size)
{
    (void)in_sizes; (void)n_in; (void)out_size;
    const float* src  = (const float*)d_in[0];
    const float* tgt  = (const float*)d_in[1];
    const float* eWi0 = (const float*)d_in[2];
    const float* eWh0 = (const float*)d_in[3];
    const float* ebi0 = (const float*)d_in[4];
    const float* ebh0 = (const float*)d_in[5];
    const float* dWi0 = (const float*)d_in[6];
    const float* dWh0 = (const float*)d_in[7];
    const float* dbi0 = (const float*)d_in[8];
    const float* dbh0 = (const float*)d_in[9];
    const float* eWi1 = (const float*)d_in[10];
    const float* eWh1 = (const float*)d_in[11];
    const float* ebi1 = (const float*)d_in[12];
    const float* ebh1 = (const float*)d_in[13];
    const float* dWi1 = (const float*)d_in[14];
    const float* dWh1 = (const float*)d_in[15];
    const float* dbi1 = (const float*)d_in[16];
    const float* dbh1 = (const float*)d_in[17];
    const float* fcW0 = (const float*)d_in[18];
    const float* fcb0 = (const float*)d_in[19];
    const float* fcW1 = (const float*)d_in[20];
    const float* fcb1 = (const float*)d_in[21];

    pack_lstm<<<512, 256>>>(eWi0, eWh0, ebi0, ebh0, 64, 0);
    pack_lstm<<<512, 256>>>(eWi1, eWh1, ebi1, ebh1, 512, 1);
    pack_lstm<<<512, 256>>>(dWh0, dWh0, dbi0, dbh0, 0, 2);   // kin=0: Wih unused
    pack_lstm<<<512, 256>>>(dWi1, dWh1, dbi1, dbh1, 512, 3);
    pack_misc<<<4096, 256>>>(src, tgt, dWi0, fcW0);
    lstm_main<<<NCTA, NTHR>>>(fcb0, fcW1, fcb1, (float*)d_out);
}